// round 8
// baseline (speedup 1.0000x reference)
#include <cuda_runtime.h>
#include <cstdint>

// SpecAugment: time-warp (±W shifted gather, zero borders) + freq mask + time mask.
// B=128, M=80, T=3000, W=80.
// One block per (b,m) row; 128 threads x 3 groups of 8 floats (384 >= 375).
// 256-bit gathers with L2::evict_last (input ~100MB ~ fits 126MB L2 across
// graph replays); output stores evict-first (.cs) so write-once data doesn't
// evict the input. All 8-float groups on the shifted path are 32B aligned
// (T, W, row pitch all multiples of 8 floats / 32 bytes).

namespace {
constexpr int B = 128;
constexpr int M = 80;
constexpr int T = 3000;
constexpr int W = 80;
constexpr int V8 = T / 8;       // 375 groups of 8 floats per row
constexpr int THREADS = 128;
constexpr int K = 3;            // groups per thread
}

__device__ __forceinline__ void ldg256_keep(const float* p, float* v) {
    asm("ld.global.nc.L2::evict_last.v8.b32 {%0,%1,%2,%3,%4,%5,%6,%7}, [%8];"
        : "=f"(v[0]), "=f"(v[1]), "=f"(v[2]), "=f"(v[3]),
          "=f"(v[4]), "=f"(v[5]), "=f"(v[6]), "=f"(v[7])
        : "l"(p));
}

__device__ __forceinline__ void st_stream4(float* p, float a, float b, float c, float d) {
    asm volatile("st.global.cs.v4.f32 [%0], {%1,%2,%3,%4};"
                 :: "l"(p), "f"(a), "f"(b), "f"(c), "f"(d));
}

__global__ void __launch_bounds__(THREADS)
specaug_kernel(const float* __restrict__ spec,
               const int*   __restrict__ centers,
               const int*   __restrict__ fs_p,
               const int*   __restrict__ fw_p,
               const int*   __restrict__ ts_p,
               const int*   __restrict__ tw_p,
               float*       __restrict__ out)
{
    const int bm = blockIdx.x;          // row id in [0, B*M)
    const int b  = bm / M;
    const int m  = bm - b * M;

    float* __restrict__ orow = out + (size_t)bm * T;

    // ---- frequency mask: whole row zero -> write-only path (no reads)
    const int f_start = __ldg(fs_p);
    const int f_width = __ldg(fw_p);
    if (m >= f_start && m < f_start + f_width) {
        #pragma unroll
        for (int k = 0; k < K; k++) {
            int v = threadIdx.x + k * THREADS;
            if (v < V8) {
                st_stream4(orow + v * 8,     0.f, 0.f, 0.f, 0.f);
                st_stream4(orow + v * 8 + 4, 0.f, 0.f, 0.f, 0.f);
            }
        }
        return;
    }

    const int c       = __ldg(centers + b);          // warp center
    const int t_start = __ldg(ts_p);
    const int t_end   = t_start + __ldg(tw_p);
    const float* __restrict__ row = spec + (size_t)bm * T;

    // ---- phase 1: 3 independent 256-bit gathers, branch-free common path.
    float vals[K][8];
    #pragma unroll
    for (int k = 0; k < K; k++) {
        const int v   = threadIdx.x + k * THREADS;
        const int t0  = v * 8;
        const int idx = (t0 + 8 <= c) ? (t0 - W) : (t0 + W);
        const bool ok = (v < V8) && (idx >= 0) && (idx + 8 <= T);
        if (ok) {
            ldg256_keep(row + idx, vals[k]);
        } else {
            #pragma unroll
            for (int j = 0; j < 8; j++) vals[k][j] = 0.f;
        }
    }

    // ---- phase 2: straddle fixup (<=1 group per row), time mask, streaming store
    #pragma unroll
    for (int k = 0; k < K; k++) {
        const int v = threadIdx.x + k * THREADS;
        if (v >= V8) break;
        const int t0 = v * 8;
        float* vp = vals[k];

        if (t0 < c && c < t0 + 8) {                  // group straddles the center
            #pragma unroll
            for (int j = 0; j < 8; j++) {
                const int t   = t0 + j;
                const int idx = (t < c) ? (t - W) : (t + W);
                vp[j] = (idx >= 0 && idx < T) ? __ldg(row + idx) : 0.f;
            }
        }

        #pragma unroll
        for (int j = 0; j < 8; j++) {
            const int t = t0 + j;
            if (t >= t_start && t < t_end) vp[j] = 0.f;
        }

        st_stream4(orow + t0,     vp[0], vp[1], vp[2], vp[3]);
        st_stream4(orow + t0 + 4, vp[4], vp[5], vp[6], vp[7]);
    }
}

extern "C" void kernel_launch(void* const* d_in, const int* in_sizes, int n_in,
                              void* d_out, int out_size)
{
    const float* spec    = (const float*)d_in[0];
    const int*   centers = (const int*)  d_in[1];
    const int*   f_start = (const int*)  d_in[2];
    const int*   f_width = (const int*)  d_in[3];
    const int*   t_start = (const int*)  d_in[4];
    const int*   t_width = (const int*)  d_in[5];
    float*       out     = (float*)      d_out;

    specaug_kernel<<<B * M, THREADS>>>(spec, centers, f_start, f_width,
                                       t_start, t_width, out);
}

// round 9
// speedup vs baseline: 1.0526x; 1.0526x over previous
#include <cuda_runtime.h>
#include <cstdint>

// SpecAugment: time-warp (±W shifted gather, zero borders) + freq mask + time mask.
// B=128, M=80, T=3000, W=80.
// R4 shape (best measured): one block per (b,m) row; 256 threads x 3 float4 groups.
// Delta vs R4: stores are evict-first (.cs) so the write-once output doesn't
// evict the ~100MB input read set from the 126MB L2 across graph replays;
// groups fully inside the time-mask band skip their load entirely.

namespace {
constexpr int B = 128;
constexpr int M = 80;
constexpr int T = 3000;
constexpr int W = 80;
constexpr int V = T / 4;        // 750 float4 groups per row
constexpr int THREADS = 256;
constexpr int K = 3;            // groups per thread
}

__device__ __forceinline__ void st_stream(float4* p, float4 v) {
    asm volatile("st.global.cs.v4.f32 [%0], {%1,%2,%3,%4};"
                 :: "l"(p), "f"(v.x), "f"(v.y), "f"(v.z), "f"(v.w));
}

__global__ void __launch_bounds__(THREADS)
specaug_kernel(const float* __restrict__ spec,
               const int*   __restrict__ centers,
               const int*   __restrict__ fs_p,
               const int*   __restrict__ fw_p,
               const int*   __restrict__ ts_p,
               const int*   __restrict__ tw_p,
               float*       __restrict__ out)
{
    const int bm = blockIdx.x;          // row id in [0, B*M)
    const int b  = bm / M;
    const int m  = bm - b * M;

    float4* __restrict__ orow = reinterpret_cast<float4*>(out) + (size_t)bm * V;

    // ---- frequency mask: whole row zero -> write-only path (no reads)
    const int f_start = __ldg(fs_p);
    const int f_width = __ldg(fw_p);
    if (m >= f_start && m < f_start + f_width) {
        const float4 z = make_float4(0.f, 0.f, 0.f, 0.f);
        #pragma unroll
        for (int k = 0; k < K; k++) {
            int v = threadIdx.x + k * THREADS;
            if (v < V) st_stream(orow + v, z);
        }
        return;
    }

    const int c       = __ldg(centers + b);          // warp center
    const int t_start = __ldg(ts_p);
    const int t_end   = t_start + __ldg(tw_p);
    const float* __restrict__ row = spec + (size_t)bm * T;

    // ---- phase 1: 3 independent float4 gathers, branch-free common path.
    // t0 and W are multiples of 4 -> shifted loads stay 16B aligned, and the
    // zero-border regions cover whole groups. Groups fully inside the time
    // mask skip the load (they'll be zeroed anyway).
    float4 vals[K];
    #pragma unroll
    for (int k = 0; k < K; k++) {
        const int v   = threadIdx.x + k * THREADS;
        const int t0  = v * 4;
        const int idx = (t0 + 4 <= c) ? (t0 - W) : (t0 + W);
        const bool masked = (t0 >= t_start) && (t0 + 4 <= t_end);
        const bool ok = (v < V) && (idx >= 0) && (idx + 4 <= T) && !masked;
        vals[k] = ok ? *reinterpret_cast<const float4*>(row + idx)
                     : make_float4(0.f, 0.f, 0.f, 0.f);
    }

    // ---- phase 2: straddle fixup (<=1 group per row), time mask, streaming store
    #pragma unroll
    for (int k = 0; k < K; k++) {
        const int v = threadIdx.x + k * THREADS;
        if (v >= V) break;
        const int t0 = v * 4;
        float4 val = vals[k];
        float* vp = reinterpret_cast<float*>(&val);

        if (t0 < c && c < t0 + 4) {                  // group straddles the center
            #pragma unroll
            for (int j = 0; j < 4; j++) {
                const int t   = t0 + j;
                const int idx = (t < c) ? (t - W) : (t + W);
                vp[j] = (idx >= 0 && idx < T) ? __ldg(row + idx) : 0.f;
            }
        }

        #pragma unroll
        for (int j = 0; j < 4; j++) {
            const int t = t0 + j;
            if (t >= t_start && t < t_end) vp[j] = 0.f;
        }

        st_stream(orow + v, val);
    }
}

extern "C" void kernel_launch(void* const* d_in, const int* in_sizes, int n_in,
                              void* d_out, int out_size)
{
    const float* spec    = (const float*)d_in[0];
    const int*   centers = (const int*)  d_in[1];
    const int*   f_start = (const int*)  d_in[2];
    const int*   f_width = (const int*)  d_in[3];
    const int*   t_start = (const int*)  d_in[4];
    const int*   t_width = (const int*)  d_in[5];
    float*       out     = (float*)      d_out;

    specaug_kernel<<<B * M, THREADS>>>(spec, centers, f_start, f_width,
                                       t_start, t_width, out);
}